// round 2
// baseline (speedup 1.0000x reference)
#include <cuda_runtime.h>
#include <cstdint>

// Problem constants (from reference): N=4096, D=128, S=32768, NUM_CLASS=500000.
#define DIM 128
#define MAX_S 32768
#define NUM_CLASS_MAX 500000

// Scratch: gathered weight rows (tf32-rounded fp32 bits) + gathered bias.
static __device__ float g_w[(size_t)MAX_S * DIM];
static __device__ float g_bias[MAX_S];
static __device__ int g_ids_is64;

__device__ __forceinline__ uint32_t f2tf32(float f) {
    uint32_t u;
    asm("cvt.rna.tf32.f32 %0, %1;" : "=r"(u) : "f"(f));
    return u;
}

// ---------------------------------------------------------------------------
// Kernel 0: detect sample_ids dtype (int32 vs int64).
// Reads only the first S/2 int64 words — in-bounds for BOTH layouts.
// int64 data: all words in [0, NUM_CLASS). int32 data: packed pairs are
// >= 2^32 unless the high id is exactly 0 (prob 2e-6 each) -> reliable.
// ---------------------------------------------------------------------------
__global__ void detect_ids_kernel(const void* __restrict__ ids, int S) {
    __shared__ int ok;
    if (threadIdx.x == 0) ok = 1;
    __syncthreads();
    const long long* p = (const long long*)ids;
    int n64 = S / 2;
    for (int s = threadIdx.x; s < n64; s += blockDim.x) {
        long long v = p[s];
        if (v < 0 || v >= NUM_CLASS_MAX) ok = 0;  // benign race: only writes 0
    }
    __syncthreads();
    if (threadIdx.x == 0) g_ids_is64 = ok;
}

__device__ __forceinline__ long long read_id(const void* ids, int s) {
    long long id = g_ids_is64 ? ((const long long*)ids)[s]
                              : (long long)((const int*)ids)[s];
    // Defensive clamp: turns any surprise into a wrong answer, not a crash.
    if (id < 0 || id >= NUM_CLASS_MAX) id = 0;
    return id;
}

// ---------------------------------------------------------------------------
// Kernel 1: gather weight[ids] -> g_w (tf32-rounded), bias[ids] -> g_bias.
// One warp per sampled row: 32 lanes x float4 = 128 floats.
// ---------------------------------------------------------------------------
__global__ void gather_kernel(const float* __restrict__ w,
                              const float* __restrict__ bias,
                              const void* __restrict__ ids,
                              int S) {
    int warp = (blockIdx.x * blockDim.x + threadIdx.x) >> 5;
    int lane = threadIdx.x & 31;
    int nwarps = (gridDim.x * blockDim.x) >> 5;
    for (int s = warp; s < S; s += nwarps) {
        long long id = read_id(ids, s);
        const float4* src = (const float4*)(w + (size_t)id * DIM);
        float4 v = src[lane];
        float4 o;
        o.x = __uint_as_float(f2tf32(v.x));
        o.y = __uint_as_float(f2tf32(v.y));
        o.z = __uint_as_float(f2tf32(v.z));
        o.w = __uint_as_float(f2tf32(v.w));
        ((float4*)(g_w + (size_t)s * DIM))[lane] = o;
        if (lane == 0) g_bias[s] = bias[id];
    }
}

// ---------------------------------------------------------------------------
// Kernel 2: tf32 GEMM  out[n][s] = dot(x[n,:], g_w[s,:]) + g_bias[s]
// BM=128, BN=128, BK=32, 256 threads (8 warps, 2x4), warp tile 64x32.
// ---------------------------------------------------------------------------
__device__ __forceinline__ void mma_tf32(float c[4], const uint32_t a[4],
                                         const uint32_t b[2]) {
    asm volatile(
        "mma.sync.aligned.m16n8k8.row.col.f32.tf32.tf32.f32 "
        "{%0,%1,%2,%3}, {%4,%5,%6,%7}, {%8,%9}, {%0,%1,%2,%3};\n"
        : "+f"(c[0]), "+f"(c[1]), "+f"(c[2]), "+f"(c[3])
        : "r"(a[0]), "r"(a[1]), "r"(a[2]), "r"(a[3]), "r"(b[0]), "r"(b[1]));
}

__global__ __launch_bounds__(256, 2)
void gemm_tf32_kernel(const float* __restrict__ x, float* __restrict__ out,
                      int N, int S) {
    __shared__ float As[128][32 + 4];   // [m][k], pad 4 -> conflict-free frag LDS
    __shared__ float Bs[128][32 + 4];   // [n][k]

    const int tid  = threadIdx.x;
    const int lane = tid & 31;
    const int wid  = tid >> 5;
    const int wm   = wid & 1;        // 2 warp rows of 64
    const int wn   = wid >> 1;       // 4 warp cols of 32
    const int gid  = lane >> 2;      // 0..7
    const int tg   = lane & 3;       // 0..3

    const int m0 = blockIdx.y * 128;
    const int n0 = blockIdx.x * 128;

    float c[4][4][4];
#pragma unroll
    for (int mi = 0; mi < 4; mi++)
#pragma unroll
        for (int ni = 0; ni < 4; ni++)
#pragma unroll
            for (int j = 0; j < 4; j++) c[mi][ni][j] = 0.0f;

    const int ldrow = tid >> 3;         // 0..31
    const int ldcol = (tid & 7) * 4;    // 0,4,...,28

    for (int k0 = 0; k0 < DIM; k0 += 32) {
#pragma unroll
        for (int p = 0; p < 4; p++) {
            int r = ldrow + p * 32;
            float4 va = *(const float4*)(x + (size_t)(m0 + r) * DIM + k0 + ldcol);
            float4 oa;
            oa.x = __uint_as_float(f2tf32(va.x));
            oa.y = __uint_as_float(f2tf32(va.y));
            oa.z = __uint_as_float(f2tf32(va.z));
            oa.w = __uint_as_float(f2tf32(va.w));
            *(float4*)&As[r][ldcol] = oa;
            float4 vb = *(const float4*)(g_w + (size_t)(n0 + r) * DIM + k0 + ldcol);
            *(float4*)&Bs[r][ldcol] = vb;   // already tf32-rounded
        }
        __syncthreads();

#pragma unroll
        for (int kk = 0; kk < 32; kk += 8) {
            uint32_t a[4][4], b[4][2];
#pragma unroll
            for (int mi = 0; mi < 4; mi++) {
                int rb = wm * 64 + mi * 16 + gid;
                a[mi][0] = __float_as_uint(As[rb][kk + tg]);
                a[mi][1] = __float_as_uint(As[rb + 8][kk + tg]);
                a[mi][2] = __float_as_uint(As[rb][kk + tg + 4]);
                a[mi][3] = __float_as_uint(As[rb + 8][kk + tg + 4]);
            }
#pragma unroll
            for (int ni = 0; ni < 4; ni++) {
                int cb = wn * 32 + ni * 8 + gid;
                b[ni][0] = __float_as_uint(Bs[cb][kk + tg]);
                b[ni][1] = __float_as_uint(Bs[cb][kk + tg + 4]);
            }
#pragma unroll
            for (int mi = 0; mi < 4; mi++)
#pragma unroll
                for (int ni = 0; ni < 4; ni++)
                    mma_tf32(c[mi][ni], a[mi], b[ni]);
        }
        __syncthreads();
    }

    // --- epilogue: add bias, store float2 pairs ---
#pragma unroll
    for (int mi = 0; mi < 4; mi++) {
        int r0 = m0 + wm * 64 + mi * 16 + gid;
#pragma unroll
        for (int ni = 0; ni < 4; ni++) {
            int col = n0 + wn * 32 + ni * 8 + 2 * tg;
            float b0 = g_bias[col];
            float b1 = g_bias[col + 1];
            float2 v0 = make_float2(c[mi][ni][0] + b0, c[mi][ni][1] + b1);
            *(float2*)(out + (size_t)r0 * S + col) = v0;
            float2 v1 = make_float2(c[mi][ni][2] + b0, c[mi][ni][3] + b1);
            *(float2*)(out + (size_t)(r0 + 8) * S + col) = v1;
        }
    }
}

// ---------------------------------------------------------------------------
// Kernel 3: pass-through sample_ids after the logits block.
// extra >= 2S fp32 slots -> raw int64 packing; extra >= S -> float cast
// (ids < 500000 are exact in fp32).
// ---------------------------------------------------------------------------
__global__ void write_ids_kernel(const void* __restrict__ ids, void* out,
                                 long long base, long long extra, int S) {
    int s = blockIdx.x * blockDim.x + threadIdx.x;
    if (s >= S) return;
    long long id = read_id(ids, s);
    if (extra >= 2LL * S) {
        long long* p = (long long*)((float*)out + base);
        p[s] = id;
    } else if (extra >= (long long)S) {
        ((float*)out)[base + s] = (float)id;
    }
}

// ---------------------------------------------------------------------------
extern "C" void kernel_launch(void* const* d_in, const int* in_sizes, int n_in,
                              void* d_out, int out_size) {
    const float* x    = (const float*)d_in[0];
    const float* w    = (const float*)d_in[1];
    const float* bias = (const float*)d_in[2];
    const void*  ids  = d_in[3];

    const int N = in_sizes[0] / DIM;   // 4096
    const int S = in_sizes[3];         // 32768

    detect_ids_kernel<<<1, 256>>>(ids, S);
    gather_kernel<<<256, 256>>>(w, bias, ids, S);

    dim3 grid(S / 128, N / 128);
    gemm_tf32_kernel<<<grid, 256>>>(x, (float*)d_out, N, S);

    long long base  = (long long)N * (long long)S;
    long long extra = (long long)out_size - base;
    if (extra > 0) {
        write_ids_kernel<<<(S + 255) / 256, 256>>>(ids, d_out, base, extra, S);
    }
}